// round 14
// baseline (speedup 1.0000x reference)
#include <cuda_runtime.h>
#include <cuda_fp16.h>
#include <math.h>
#include <stdint.h>

#define Hdim 1024
#define H3   3072
#define Gdim 256
#define Ldim 128
#define NMAX 16384
#define WELEM (H3 * Hdim)

// ---------------- scratch (device globals; no allocations) ----------------
__device__ uint32_t g_msg16[NMAX * Hdim / 2];        // fp16x2 rounded message
__device__ uint32_t g_w16[2][WELEM / 2];             // fp16x2 ih weights (row-major): 0=f 1=b
__device__ uint32_t g_wfrag[2][WELEM / 2];           // fp16x2 hh weights, MMA b-fragment order
__device__ float    g_xg[2][(size_t)NMAX * H3];
__device__ float    g_h[2][2][Gdim * Hdim];          // fp32 hidden (exact carry)
__device__ uint4    g_ha4[2][2][16 * 64 * 32];       // fp16x2 hidden, MMA a-fragment order
__device__ int      g_start[Gdim + 1];
__device__ int      g_tilemax2[2];                   // per-128-graph-tile max count
__device__ unsigned g_bar4[2][2];                    // per-(dir, gtile) barrier

// ---------------- helpers ----------------
__device__ __forceinline__ uint32_t pack2h(float x, float y) {
    __half2 h = __halves2half2(__float2half_rn(x), __float2half_rn(y));
    return *reinterpret_cast<uint32_t*>(&h);
}
__device__ __forceinline__ void mma16f(float* d, const uint32_t* a, const uint32_t* b) {
    asm volatile(
        "mma.sync.aligned.m16n8k16.row.col.f32.f16.f16.f32 "
        "{%0,%1,%2,%3}, {%4,%5,%6,%7}, {%8,%9}, {%0,%1,%2,%3};\n"
        : "+f"(d[0]), "+f"(d[1]), "+f"(d[2]), "+f"(d[3])
        : "r"(a[0]), "r"(a[1]), "r"(a[2]), "r"(a[3]), "r"(b[0]), "r"(b[1]));
}
// a-fragment uint32 index for h value pair (g, j), (g, j+1) [j even]
__device__ __forceinline__ int ha_idx(int g, int j) {
    return ((g >> 4) * 64 + (j >> 4)) * 128
         + ((((g & 7) << 2) | ((j >> 1) & 3)) << 2)
         + (((j >> 3) & 1) << 1) + ((g >> 3) & 1);
}

// ---------------- meta: segment starts + tile max + barrier reset ----------------
__global__ void k_meta(const int* __restrict__ batch, int n) {
    __shared__ int smax[2];
    int g = threadIdx.x;
    if (g < 4) ((unsigned*)g_bar4)[g] = 0;
    if (g < 2) smax[g] = 0;
    __syncthreads();
    if (g <= Gdim) {
        int lo = 0, hi = n;
        while (lo < hi) {
            int mid = (lo + hi) >> 1;
            if (batch[mid] < g) lo = mid + 1; else hi = mid;
        }
        g_start[g] = lo;
    }
    __syncthreads();
    if (g < Gdim) {
        int gg = g + 1;
        int lo = 0, hi = n;
        while (lo < hi) {
            int mid = (lo + hi) >> 1;
            if (batch[mid] < gg) lo = mid + 1; else hi = mid;
        }
        int cnt = lo - g_start[g];
        atomicMax(&smax[g >> 7], cnt);
    }
    __syncthreads();
    if (g < 2) g_tilemax2[g] = smax[g];
}

// ---------------- ih weight round (fp32 -> fp16, row-major) ----------------
__global__ void k_round_w(const float* __restrict__ w0, const float* __restrict__ w1) {
    int which = blockIdx.y;
    const float* src = which == 0 ? w0 : w1;
    int i = blockIdx.x * blockDim.x + threadIdx.x;
    if (i >= WELEM / 4) return;
    float4 v = ((const float4*)src)[i];
    ((uint2*)g_w16[which])[i] = make_uint2(pack2h(v.x, v.y), pack2h(v.z, v.w));
}

// ---------------- hh weight pack (fp32 -> fp16, MMA b-fragment order) ----------------
// uint2 index i = ((jo*3 + gt)*64 + kf)*32 + lane
// j = jo*8 + (lane>>2), k = kf*16 + (lane&3)*2, row = gt*Hdim + j
// uint2 = { pack(W[j][k],W[j][k+1]), pack(W[j][k+8],W[j][k+9]) }
__global__ void k_pack_whh(const float* __restrict__ wf, const float* __restrict__ wb) {
    int dir = blockIdx.y;
    const float* W = dir ? wb : wf;
    int i = blockIdx.x * blockDim.x + threadIdx.x;
    if (i >= WELEM / 4) return;
    int lane = i & 31;
    int kf = (i >> 5) & 63;
    int rest = i >> 11;          // jo*3 + gt
    int gt = rest % 3;
    int jo = rest / 3;
    int j = jo * 8 + (lane >> 2);
    int k = kf * 16 + (lane & 3) * 2;
    const float* row = &W[(size_t)(gt * Hdim + j) * Hdim];
    float2 v0 = *(const float2*)&row[k];
    float2 v1 = *(const float2*)&row[k + 8];
    ((uint2*)g_wfrag[dir])[i] = make_uint2(pack2h(v0.x, v0.y), pack2h(v1.x, v1.y));
}

// ---------------- message = relu(h_atom + bias) -> fp16 ----------------
__global__ void k_message(const float* __restrict__ h_atom,
                          const float* __restrict__ bias, int n4) {
    int i = blockIdx.x * blockDim.x + threadIdx.x;
    if (i >= n4) return;
    float4 v = ((const float4*)h_atom)[i];
    float4 b = ((const float4*)bias)[i & (Hdim / 4 - 1)];
    v.x = fmaxf(v.x + b.x, 0.f);
    v.y = fmaxf(v.y + b.y, 0.f);
    v.z = fmaxf(v.z + b.z, 0.f);
    v.w = fmaxf(v.w + b.w, 0.f);
    ((uint2*)g_msg16)[i] = make_uint2(pack2h(v.x, v.y), pack2h(v.z, v.w));
}

// ---------------- h0 = segment max (4-row MLP); fp32 + a-frag, both dirs ----------------
__global__ void k_h0(const float* __restrict__ h_atom) {
    int g = blockIdx.x;
    int c = threadIdx.x * 4;
    int s0 = g_start[g], s1 = g_start[g + 1];
    float4 m0 = make_float4(-3.4e38f, -3.4e38f, -3.4e38f, -3.4e38f);
    float4 m1 = m0, m2 = m0, m3 = m0;
    int r = s0;
    for (; r + 4 <= s1; r += 4) {
        float4 v0 = *(const float4*)&h_atom[(size_t)(r + 0) * Hdim + c];
        float4 v1 = *(const float4*)&h_atom[(size_t)(r + 1) * Hdim + c];
        float4 v2 = *(const float4*)&h_atom[(size_t)(r + 2) * Hdim + c];
        float4 v3 = *(const float4*)&h_atom[(size_t)(r + 3) * Hdim + c];
        m0.x = fmaxf(m0.x, v0.x); m0.y = fmaxf(m0.y, v0.y); m0.z = fmaxf(m0.z, v0.z); m0.w = fmaxf(m0.w, v0.w);
        m1.x = fmaxf(m1.x, v1.x); m1.y = fmaxf(m1.y, v1.y); m1.z = fmaxf(m1.z, v1.z); m1.w = fmaxf(m1.w, v1.w);
        m2.x = fmaxf(m2.x, v2.x); m2.y = fmaxf(m2.y, v2.y); m2.z = fmaxf(m2.z, v2.z); m2.w = fmaxf(m2.w, v2.w);
        m3.x = fmaxf(m3.x, v3.x); m3.y = fmaxf(m3.y, v3.y); m3.z = fmaxf(m3.z, v3.z); m3.w = fmaxf(m3.w, v3.w);
    }
    for (; r < s1; r++) {
        float4 v = *(const float4*)&h_atom[(size_t)r * Hdim + c];
        m0.x = fmaxf(m0.x, v.x); m0.y = fmaxf(m0.y, v.y); m0.z = fmaxf(m0.z, v.z); m0.w = fmaxf(m0.w, v.w);
    }
    float4 m;
    m.x = fmaxf(fmaxf(m0.x, m1.x), fmaxf(m2.x, m3.x));
    m.y = fmaxf(fmaxf(m0.y, m1.y), fmaxf(m2.y, m3.y));
    m.z = fmaxf(fmaxf(m0.z, m1.z), fmaxf(m2.z, m3.z));
    m.w = fmaxf(fmaxf(m0.w, m1.w), fmaxf(m2.w, m3.w));
    if (s1 == s0) m = make_float4(0.f, 0.f, 0.f, 0.f);
    int fi = g * Hdim + c;
    uint32_t v01 = pack2h(m.x, m.y);
    uint32_t v23 = pack2h(m.z, m.w);
    int idx = ha_idx(g, c);
#pragma unroll
    for (int d = 0; d < 2; d++) {
        *(float4*)&g_h[d][0][fi] = m;
        uint32_t* hao = (uint32_t*)g_ha4[d][0];
        hao[idx] = v01;
        hao[idx + 4] = v23;   // pair (c+2,c+3): kpair+1 -> +4
    }
}

// =====================================================================
// Input GEMM (fp16): XG[n x 3072] = msg @ W_ih^T + b_ih
// Block 128m x 128n, K-chunk 16, 8 warps (2m x 4n), warp 64x32.
// =====================================================================
__global__ void __launch_bounds__(256) k_gemm_f16(
    const float* __restrict__ bi_f, const float* __restrict__ bi_b, int n)
{
    __shared__ uint32_t sA[2048], sB[2048];
    int dir = blockIdx.z;
    const uint32_t* W = g_w16[dir];
    const float* Bv = dir ? bi_b : bi_f;
    float* XG = g_xg[dir];
    int n0 = blockIdx.x * 128;
    int m0 = blockIdx.y * 128;
    int tid = threadIdx.x, lane = tid & 31, wid = tid >> 5;
    int wm = wid >> 2, wn = wid & 3;

    int ar = tid >> 1, ao = tid & 1;
    int br = tid >> 1, bo = tid & 1;

    float acc[4][4][4];
#pragma unroll
    for (int m = 0; m < 4; m++)
#pragma unroll
        for (int q = 0; q < 4; q++)
#pragma unroll
            for (int e = 0; e < 4; e++) acc[m][q][e] = 0.f;

    uint4 pA, pB;

    auto ld = [&](int k0) {
        int rg = m0 + ar;
        if (rg < n) pA = *(const uint4*)&g_msg16[rg * (Hdim / 2) + (k0 + ao * 8) / 2];
        else        pA = make_uint4(0, 0, 0, 0);
        pB = *(const uint4*)&W[(size_t)(n0 + br) * (Hdim / 2) + (k0 + bo * 8) / 2];
    };
    auto st = [&](int buf) {
        int mfr = ar >> 4, rh = (ar >> 3) & 1, reg = ao * 2 + rh;
        int base = buf * 1024 + (mfr * 32 + (ar & 7) * 4) * 4 + reg;
        const uint32_t* p = (const uint32_t*)&pA;
#pragma unroll
        for (int i = 0; i < 4; i++) sA[base + i * 4] = p[i];
        int nfr = br >> 3, nl = br & 7;
        int base2 = buf * 1024 + (nfr * 32 + nl * 4) * 2 + bo;
        const uint32_t* q = (const uint32_t*)&pB;
#pragma unroll
        for (int i = 0; i < 4; i++) sB[base2 + i * 2] = q[i];
    };
    auto comp = [&](int buf) {
        uint4 a[4]; uint2 b[4];
#pragma unroll
        for (int m = 0; m < 4; m++)
            a[m] = *(const uint4*)&sA[buf * 1024 + ((wm * 4 + m) * 32 + lane) * 4];
#pragma unroll
        for (int q = 0; q < 4; q++)
            b[q] = *(const uint2*)&sB[buf * 1024 + ((wn * 4 + q) * 32 + lane) * 2];
#pragma unroll
        for (int m = 0; m < 4; m++)
#pragma unroll
            for (int q = 0; q < 4; q++)
                mma16f(acc[m][q], (const uint32_t*)&a[m], (const uint32_t*)&b[q]);
    };

    ld(0); st(0); __syncthreads();
    for (int c = 0; c < Hdim / 16; c++) {
        int buf = c & 1;
        if (c + 1 < Hdim / 16) ld((c + 1) * 16);
        comp(buf);
        if (c + 1 < Hdim / 16) { st(buf ^ 1); __syncthreads(); }
    }

#pragma unroll
    for (int m = 0; m < 4; m++)
#pragma unroll
        for (int half = 0; half < 2; half++) {
            int row = m0 + wm * 64 + m * 16 + (lane >> 2) + half * 8;
            if (row < n) {
#pragma unroll
                for (int q = 0; q < 4; q++) {
                    int col = n0 + wn * 32 + q * 8 + (lane & 3) * 2;
                    float2 o;
                    o.x = acc[m][q][half * 2 + 0] + Bv[col];
                    o.y = acc[m][q][half * 2 + 1] + Bv[col + 1];
                    *(float2*)&XG[(size_t)row * H3 + col] = o;
                }
            }
        }
}

// =====================================================================
// PERSISTENT zero-sync GRU step kernel.
// CTA tile 128g x 32j (x3 gates = 96n), grid (32 j, 2 g, 2 dir) = 128 CTAs.
// 8 warps: warp wm owns m16 frag wm x all 12 n-frags (12 HMMA per kf).
// A: direct __ldcg uint4 from fragment-packed g_ha4 (2-slot pipeline).
// B: direct __ldg uint2 from fragment-packed g_wfrag (L1-resident slab).
// NO shared memory, NO __syncthreads in the mainloop.
// Per-(dir,gtile) barrier (32 CTAs); forward tile retires wholesale.
// =====================================================================
__global__ void __launch_bounds__(256) k_step_persist(
    const float* __restrict__ bhh_f, const float* __restrict__ bih_f,
    const float* __restrict__ bhh_b, const float* __restrict__ bih_b,
    float* __restrict__ out)
{
    int dir = blockIdx.z;
    int bx = blockIdx.x, gy = blockIdx.y;
    const float* Bh = dir ? bhh_b : bhh_f;
    const float* Bi = dir ? bih_b : bih_f;
    const float* xg = g_xg[dir];
    const uint2* WB = (const uint2*)g_wfrag[dir];
    int j0 = bx * 32, g0 = gy * 128;
    int tid = threadIdx.x, lane = tid & 31, wm = tid >> 5;
    int tmax = g_tilemax2[gy];

    // B fragment bases (uint2 index), 12 per warp
    int bbase[4][3];
#pragma unroll
    for (int joL = 0; joL < 4; joL++)
#pragma unroll
        for (int gt = 0; gt < 3; gt++)
            bbase[joL][gt] = (((bx * 4 + joL) * 3 + gt) * 64) * 32 + lane;

    // A fragment base (uint4 index)
    int g16 = gy * 8 + wm;
    int abase = g16 * 64 * 32 + lane;

    // epilogue segment invariants
    int gA[2], stA[2], cntA[2];
#pragma unroll
    for (int half = 0; half < 2; half++) {
        int g = g0 + wm * 16 + (lane >> 2) + half * 8;
        gA[half] = g;
        stA[half] = g_start[g];
        cntA[half] = g_start[g + 1] - stA[half];
    }

    for (int s = 0; s < Ldim; s++) {
        int tstep = dir ? (Ldim - 1 - s) : s;
        // whole (dir0, gtile) group retires together; its barrier is unused after.
        if (dir == 0 && tstep >= tmax) return;

        int par = s & 1;
        const uint4* ha  = g_ha4[dir][par];
        uint32_t*    hao = (uint32_t*)g_ha4[dir][par ^ 1];
        const float* hin  = g_h[dir][par];
        float*       hout = g_h[dir][par ^ 1];

        float acc[4][3][4];
#pragma unroll
        for (int joL = 0; joL < 4; joL++)
#pragma unroll
            for (int gt = 0; gt < 3; gt++)
#pragma unroll
                for (int e = 0; e < 4; e++) acc[joL][gt][e] = 0.f;

        uint4 a[2][2];
        a[0][0] = __ldcg(ha + abase + 0 * 32);
        a[0][1] = __ldcg(ha + abase + 1 * 32);
        a[1][0] = __ldcg(ha + abase + 2 * 32);
        a[1][1] = __ldcg(ha + abase + 3 * 32);

        for (int c = 0; c < 32; c++) {
            int sl = c & 1;
#pragma unroll
            for (int kfi = 0; kfi < 2; kfi++) {
                int kf = c * 2 + kfi;
                uint2 b[4][3];
#pragma unroll
                for (int joL = 0; joL < 4; joL++)
#pragma unroll
                    for (int gt = 0; gt < 3; gt++)
                        b[joL][gt] = __ldg(WB + bbase[joL][gt] + kf * 32);
#pragma unroll
                for (int joL = 0; joL < 4; joL++)
#pragma unroll
                    for (int gt = 0; gt < 3; gt++)
                        mma16f(acc[joL][gt], (const uint32_t*)&a[sl][kfi],
                               (const uint32_t*)&b[joL][gt]);
            }
            if (c + 2 < 32) {
                a[sl][0] = __ldcg(ha + abase + ((c + 2) * 2 + 0) * 32);
                a[sl][1] = __ldcg(ha + abase + ((c + 2) * 2 + 1) * 32);
            }
        }

        // ---- fused gate epilogue + a-frag pack + scatter ----
#pragma unroll
        for (int joL = 0; joL < 4; joL++) {
            int j = j0 + joL * 8 + (lane & 3) * 2;
#pragma unroll
            for (int half = 0; half < 2; half++) {
                int g = gA[half];
                bool valid = (tstep < cntA[half]);
                size_t ab = (size_t)(stA[half] + tstep) * H3;
                float hv[2];
#pragma unroll
                for (int cp = 0; cp < 2; cp++) {
                    int jj = j + cp;
                    float xr, xz, xn;
                    if (valid) {
                        xr = xg[ab + jj];
                        xz = xg[ab + Hdim + jj];
                        xn = xg[ab + 2 * Hdim + jj];
                    } else {
                        xr = Bi[jj]; xz = Bi[Hdim + jj]; xn = Bi[2 * Hdim + jj];
                    }
                    int e = half * 2 + cp;
                    float r  = 1.f / (1.f + expf(-(xr + acc[joL][0][e] + Bh[jj])));
                    float z  = 1.f / (1.f + expf(-(xz + acc[joL][1][e] + Bh[Hdim + jj])));
                    float nn = tanhf(xn + r * (acc[joL][2][e] + Bh[2 * Hdim + jj]));
                    float hp = __ldcg(&hin[g * Hdim + jj]);
                    hv[cp] = (1.f - z) * nn + z * hp;
                    hout[g * Hdim + jj] = hv[cp];
                    if (valid)
                        out[(size_t)(stA[half] + tstep) * (2 * Hdim) + (size_t)dir * Hdim + jj] = hv[cp];
                }
                hao[ha_idx(g, j)] = pack2h(hv[0], hv[1]);
            }
        }

        // ---- per-(dir, gtile) barrier: 32 CTAs ----
        if (s + 1 < Ldim) {
            __threadfence();
            __syncthreads();
            if (tid == 0) {
                unsigned tgt = (unsigned)(s + 1) * 32u;
                atomicAdd(&g_bar4[dir][gy], 1u);
                while (*(volatile unsigned*)&g_bar4[dir][gy] < tgt) { }
            }
            __syncthreads();
        }
    }
}

// ---------------- host launcher ----------------
extern "C" void kernel_launch(void* const* d_in, const int* in_sizes, int n_in,
                              void* d_out, int out_size)
{
    int nAtoms = in_sizes[0] / Hdim;

    const float* h_atom = (const float*)d_in[0];
    int iBatch, iBias, iWihF, iWhhF, iBihF, iBhhF, iWihB, iWhhB, iBihB, iBhhB;
    if (in_sizes[1] == nAtoms) {
        iBatch = 1; iBias = 2; iWihF = 3; iWhhF = 4; iBihF = 5; iBhhF = 6;
        iWihB = 7; iWhhB = 8; iBihB = 9; iBhhB = 10;
    } else {
        iBias = 1; iWihF = 2; iWhhF = 3; iBihF = 4; iBhhF = 5;
        iWihB = 6; iWhhB = 7; iBihB = 8; iBhhB = 9; iBatch = 10;
    }

    const int*   batch = (const int*)d_in[iBatch];
    const float* bias  = (const float*)d_in[iBias];
    const float* wihf  = (const float*)d_in[iWihF];
    const float* whhf  = (const float*)d_in[iWhhF];
    const float* bihf  = (const float*)d_in[iBihF];
    const float* bhhf  = (const float*)d_in[iBhhF];
    const float* wihb  = (const float*)d_in[iWihB];
    const float* whhb  = (const float*)d_in[iWhhB];
    const float* bihb  = (const float*)d_in[iBihB];
    const float* bhhb  = (const float*)d_in[iBhhB];
    float* out = (float*)d_out;

    k_meta<<<1, 512>>>(batch, nAtoms);

    dim3 gw(WELEM / 4 / 256, 2);
    k_round_w<<<gw, 256>>>(wihf, wihb);

    dim3 gp(WELEM / 4 / 256, 2);
    k_pack_whh<<<gp, 256>>>(whhf, whhb);

    int n4 = nAtoms * Hdim / 4;
    k_message<<<(n4 + 255) / 256, 256>>>(h_atom, bias, n4);

    k_h0<<<Gdim, 256>>>(h_atom);

    dim3 gg(H3 / 128, (nAtoms + 127) / 128, 2);
    k_gemm_f16<<<gg, 256>>>(bihf, bihb, nAtoms);

    // persistent zero-sync recurrence: 128 CTAs, per-(dir,gtile) barriers
    dim3 gs(Hdim / 32, Gdim / 128, 2);
    k_step_persist<<<gs, 256>>>(bhhf, bihf, bhhb, bihb, out);
}

// round 15
// speedup vs baseline: 1.1756x; 1.1756x over previous
#include <cuda_runtime.h>
#include <cuda_fp16.h>
#include <math.h>
#include <stdint.h>

#define Hdim 1024
#define H3   3072
#define Gdim 256
#define Ldim 128
#define NMAX 16384
#define WELEM (H3 * Hdim)
#define STEP_CTAS 256        // 32 j-tiles x 4 g-tiles x 2 dirs

// ---------------- scratch (device globals; no allocations) ----------------
__device__ uint32_t g_msg16[NMAX * Hdim / 2];        // fp16x2 rounded message
__device__ uint32_t g_w16[4][WELEM / 2];             // fp16x2 weights: 0=ih_f 1=hh_f 2=ih_b 3=hh_b
__device__ float    g_xg[2][(size_t)NMAX * H3];
__device__ float    g_h[2][2][Gdim * Hdim];          // fp32 hidden (exact carry)
__device__ uint32_t g_h16[2][2][Gdim * Hdim / 2];    // fp16x2 rounded hidden (mma operand)
__device__ int      g_start[Gdim + 1];
__device__ int      g_tilemax[Gdim / 64];            // per-64-graph-tile max count
__device__ unsigned g_barcnt;                        // persistent grid barrier

// ---------------- helpers ----------------
__device__ __forceinline__ uint32_t pack2h(float x, float y) {
    __half2 h = __halves2half2(__float2half_rn(x), __float2half_rn(y));
    return *reinterpret_cast<uint32_t*>(&h);
}
__device__ __forceinline__ void mma16f(float* d, const uint32_t* a, const uint32_t* b) {
    asm volatile(
        "mma.sync.aligned.m16n8k16.row.col.f32.f16.f16.f32 "
        "{%0,%1,%2,%3}, {%4,%5,%6,%7}, {%8,%9}, {%0,%1,%2,%3};\n"
        : "+f"(d[0]), "+f"(d[1]), "+f"(d[2]), "+f"(d[3])
        : "r"(a[0]), "r"(a[1]), "r"(a[2]), "r"(a[3]), "r"(b[0]), "r"(b[1]));
}

// ---------------- meta: segment starts + per-tile max + barrier reset ----------------
__global__ void k_meta(const int* __restrict__ batch, int n) {
    __shared__ int smax[Gdim / 64];
    int g = threadIdx.x;
    if (g == 0) g_barcnt = 0;
    if (g < Gdim / 64) smax[g] = 0;
    __syncthreads();
    if (g <= Gdim) {
        int lo = 0, hi = n;
        while (lo < hi) {
            int mid = (lo + hi) >> 1;
            if (batch[mid] < g) lo = mid + 1; else hi = mid;
        }
        g_start[g] = lo;
    }
    __syncthreads();
    if (g < Gdim) {
        int gg = g + 1;
        int lo = 0, hi = n;
        while (lo < hi) {
            int mid = (lo + hi) >> 1;
            if (batch[mid] < gg) lo = mid + 1; else hi = mid;
        }
        int cnt = lo - g_start[g];
        atomicMax(&smax[g >> 6], cnt);
    }
    __syncthreads();
    if (g < Gdim / 64) g_tilemax[g] = smax[g];
}

// ---------------- weight round (fp32 -> fp16) ----------------
__global__ void k_round_w(const float* __restrict__ w0, const float* __restrict__ w1,
                          const float* __restrict__ w2, const float* __restrict__ w3) {
    int which = blockIdx.y;
    const float* src = which == 0 ? w0 : which == 1 ? w1 : which == 2 ? w2 : w3;
    int i = blockIdx.x * blockDim.x + threadIdx.x;
    if (i >= WELEM / 4) return;
    float4 v = ((const float4*)src)[i];
    ((uint2*)g_w16[which])[i] = make_uint2(pack2h(v.x, v.y), pack2h(v.z, v.w));
}

// ---------------- message = relu(h_atom + bias) -> fp16 ----------------
__global__ void k_message(const float* __restrict__ h_atom,
                          const float* __restrict__ bias, int n4) {
    int i = blockIdx.x * blockDim.x + threadIdx.x;
    if (i >= n4) return;
    float4 v = ((const float4*)h_atom)[i];
    float4 b = ((const float4*)bias)[i & (Hdim / 4 - 1)];
    v.x = fmaxf(v.x + b.x, 0.f);
    v.y = fmaxf(v.y + b.y, 0.f);
    v.z = fmaxf(v.z + b.z, 0.f);
    v.w = fmaxf(v.w + b.w, 0.f);
    ((uint2*)g_msg16)[i] = make_uint2(pack2h(v.x, v.y), pack2h(v.z, v.w));
}

// ---------------- h0 = segment max (4-row MLP); fp32 + fp16, both dirs ----------------
__global__ void k_h0(const float* __restrict__ h_atom) {
    int g = blockIdx.x;
    int c = threadIdx.x * 4;
    int s0 = g_start[g], s1 = g_start[g + 1];
    float4 m0 = make_float4(-3.4e38f, -3.4e38f, -3.4e38f, -3.4e38f);
    float4 m1 = m0, m2 = m0, m3 = m0;
    int r = s0;
    for (; r + 4 <= s1; r += 4) {
        float4 v0 = *(const float4*)&h_atom[(size_t)(r + 0) * Hdim + c];
        float4 v1 = *(const float4*)&h_atom[(size_t)(r + 1) * Hdim + c];
        float4 v2 = *(const float4*)&h_atom[(size_t)(r + 2) * Hdim + c];
        float4 v3 = *(const float4*)&h_atom[(size_t)(r + 3) * Hdim + c];
        m0.x = fmaxf(m0.x, v0.x); m0.y = fmaxf(m0.y, v0.y); m0.z = fmaxf(m0.z, v0.z); m0.w = fmaxf(m0.w, v0.w);
        m1.x = fmaxf(m1.x, v1.x); m1.y = fmaxf(m1.y, v1.y); m1.z = fmaxf(m1.z, v1.z); m1.w = fmaxf(m1.w, v1.w);
        m2.x = fmaxf(m2.x, v2.x); m2.y = fmaxf(m2.y, v2.y); m2.z = fmaxf(m2.z, v2.z); m2.w = fmaxf(m2.w, v2.w);
        m3.x = fmaxf(m3.x, v3.x); m3.y = fmaxf(m3.y, v3.y); m3.z = fmaxf(m3.z, v3.z); m3.w = fmaxf(m3.w, v3.w);
    }
    for (; r < s1; r++) {
        float4 v = *(const float4*)&h_atom[(size_t)r * Hdim + c];
        m0.x = fmaxf(m0.x, v.x); m0.y = fmaxf(m0.y, v.y); m0.z = fmaxf(m0.z, v.z); m0.w = fmaxf(m0.w, v.w);
    }
    float4 m;
    m.x = fmaxf(fmaxf(m0.x, m1.x), fmaxf(m2.x, m3.x));
    m.y = fmaxf(fmaxf(m0.y, m1.y), fmaxf(m2.y, m3.y));
    m.z = fmaxf(fmaxf(m0.z, m1.z), fmaxf(m2.z, m3.z));
    m.w = fmaxf(fmaxf(m0.w, m1.w), fmaxf(m2.w, m3.w));
    if (s1 == s0) m = make_float4(0.f, 0.f, 0.f, 0.f);
    int fi = g * Hdim + c;
    uint2 p = make_uint2(pack2h(m.x, m.y), pack2h(m.z, m.w));
#pragma unroll
    for (int d = 0; d < 2; d++) {
        *(float4*)&g_h[d][0][fi] = m;
        ((uint2*)g_h16[d][0])[fi / 4] = p;
    }
}

// =====================================================================
// Input GEMM (fp16): XG[n x 3072] = msg @ W_ih^T + b_ih
// Block 128m x 128n, K-chunk 16, 8 warps (2m x 4n), warp 64x32.
// =====================================================================
__global__ void __launch_bounds__(256) k_gemm_f16(
    const float* __restrict__ bi_f, const float* __restrict__ bi_b, int n)
{
    __shared__ uint32_t sA[2048], sB[2048];
    int dir = blockIdx.z;
    const uint32_t* W = g_w16[dir * 2];
    const float* Bv = dir ? bi_b : bi_f;
    float* XG = g_xg[dir];
    int n0 = blockIdx.x * 128;
    int m0 = blockIdx.y * 128;
    int tid = threadIdx.x, lane = tid & 31, wid = tid >> 5;
    int wm = wid >> 2, wn = wid & 3;

    int ar = tid >> 1, ao = tid & 1;
    int br = tid >> 1, bo = tid & 1;

    float acc[4][4][4];
#pragma unroll
    for (int m = 0; m < 4; m++)
#pragma unroll
        for (int q = 0; q < 4; q++)
#pragma unroll
            for (int e = 0; e < 4; e++) acc[m][q][e] = 0.f;

    uint4 pA, pB;

    auto ld = [&](int k0) {
        int rg = m0 + ar;
        if (rg < n) pA = *(const uint4*)&g_msg16[rg * (Hdim / 2) + (k0 + ao * 8) / 2];
        else        pA = make_uint4(0, 0, 0, 0);
        pB = *(const uint4*)&W[(size_t)(n0 + br) * (Hdim / 2) + (k0 + bo * 8) / 2];
    };
    auto st = [&](int buf) {
        int mfr = ar >> 4, rh = (ar >> 3) & 1, reg = ao * 2 + rh;
        int base = buf * 1024 + (mfr * 32 + (ar & 7) * 4) * 4 + reg;
        const uint32_t* p = (const uint32_t*)&pA;
#pragma unroll
        for (int i = 0; i < 4; i++) sA[base + i * 4] = p[i];
        int nfr = br >> 3, nl = br & 7;
        int base2 = buf * 1024 + (nfr * 32 + nl * 4) * 2 + bo;
        const uint32_t* q = (const uint32_t*)&pB;
#pragma unroll
        for (int i = 0; i < 4; i++) sB[base2 + i * 2] = q[i];
    };
    auto comp = [&](int buf) {
        uint4 a[4]; uint2 b[4];
#pragma unroll
        for (int m = 0; m < 4; m++)
            a[m] = *(const uint4*)&sA[buf * 1024 + ((wm * 4 + m) * 32 + lane) * 4];
#pragma unroll
        for (int q = 0; q < 4; q++)
            b[q] = *(const uint2*)&sB[buf * 1024 + ((wn * 4 + q) * 32 + lane) * 2];
#pragma unroll
        for (int m = 0; m < 4; m++)
#pragma unroll
            for (int q = 0; q < 4; q++)
                mma16f(acc[m][q], (const uint32_t*)&a[m], (const uint32_t*)&b[q]);
    };

    ld(0); st(0); __syncthreads();
    for (int c = 0; c < Hdim / 16; c++) {
        int buf = c & 1;
        if (c + 1 < Hdim / 16) ld((c + 1) * 16);
        comp(buf);
        if (c + 1 < Hdim / 16) { st(buf ^ 1); __syncthreads(); }
    }

#pragma unroll
    for (int m = 0; m < 4; m++)
#pragma unroll
        for (int half = 0; half < 2; half++) {
            int row = m0 + wm * 64 + m * 16 + (lane >> 2) + half * 8;
            if (row < n) {
#pragma unroll
                for (int q = 0; q < 4; q++) {
                    int col = n0 + wn * 32 + q * 8 + (lane & 3) * 2;
                    float2 o;
                    o.x = acc[m][q][half * 2 + 0] + Bv[col];
                    o.y = acc[m][q][half * 2 + 1] + Bv[col + 1];
                    *(float2*)&XG[(size_t)row * H3 + col] = o;
                }
            }
        }
}

// =====================================================================
// PERSISTENT GRU step kernel (R12 config, K-chunk 64).
// CTA tile 64g x 96n, 16 iterations of K=64, 2 smem buffers (40 KB),
// 1-deep register prefetch. grid (32 j, 4 g, 2 dir) = 256 CTAs, 2/SM.
// Grid barrier between steps; fwd-inactive CTAs skip work, still arrive.
// =====================================================================
#define NCH 16   // 1024 / 64

__global__ void __launch_bounds__(256, 2) k_step_persist(
    const float* __restrict__ bhh_f, const float* __restrict__ bih_f,
    const float* __restrict__ bhh_b, const float* __restrict__ bih_b,
    float* __restrict__ out)
{
    __shared__ uint32_t sA[2 * 2048], sB[2 * 3072];
    int dir = blockIdx.z;
    const uint32_t* W = g_w16[dir * 2 + 1];
    const float* Bh = dir ? bhh_b : bhh_f;
    const float* Bi = dir ? bih_b : bih_f;
    const float* xg = g_xg[dir];
    int j0 = blockIdx.x * 32;
    int g0 = blockIdx.y * 64;
    int tid = threadIdx.x, lane = tid & 31, wid = tid >> 5;
    int wm = wid >> 2, wn = wid & 3;
    int tmax = g_tilemax[blockIdx.y];

    // A loader (invariant): 256 threads, two uint4 each: row ar, octets aoct, aoct+4
    int ar = tid >> 2, aoct = tid & 3;
    // B loader (invariant): tid<192, four uint4 each: row br, k32-half bk
    bool hasB = tid < 192;
    int br = tid >> 1, bk = tid & 1;
    const uint32_t* Wrow = &W[(size_t)((br >> 5) * Hdim + j0 + (br & 31)) * (Hdim / 2)];

    // epilogue invariants
    int jj0 = j0 + wn * 8 + (lane & 3) * 2;
    float bhv[6], biv[6];
#pragma unroll
    for (int t3 = 0; t3 < 3; t3++) {
        bhv[t3 * 2 + 0] = Bh[t3 * Hdim + jj0];
        bhv[t3 * 2 + 1] = Bh[t3 * Hdim + jj0 + 1];
        biv[t3 * 2 + 0] = Bi[t3 * Hdim + jj0];
        biv[t3 * 2 + 1] = Bi[t3 * Hdim + jj0 + 1];
    }
    int gE[4], stE[4], cntE[4];
#pragma unroll
    for (int m = 0; m < 2; m++)
#pragma unroll
        for (int half = 0; half < 2; half++) {
            int idx = m * 2 + half;
            int g = g0 + (wm * 2 + m) * 16 + (lane >> 2) + half * 8;
            gE[idx] = g;
            stE[idx] = g_start[g];
            cntE[idx] = g_start[g + 1] - stE[idx];
        }

    uint4 rA0, rA1, rB[4];

    for (int s = 0; s < Ldim; s++) {
        int tstep = dir ? (Ldim - 1 - s) : s;
        bool active = !(dir == 0 && tstep >= tmax);
        if (active) {
            int par = s & 1;
            const float*    hin  = g_h[dir][par];
            float*          hout = g_h[dir][par ^ 1];
            const uint32_t* h16  = g_h16[dir][par];
            uint32_t*       ho16 = g_h16[dir][par ^ 1];

            float acc[2][3][4];
#pragma unroll
            for (int m = 0; m < 2; m++)
#pragma unroll
                for (int gt = 0; gt < 3; gt++)
#pragma unroll
                    for (int e = 0; e < 4; e++) acc[m][gt][e] = 0.f;

            auto ld = [&](int c) {
                const uint32_t* ha = &h16[(g0 + ar) * (Hdim / 2) + c * 32 + aoct * 4];
                rA0 = __ldcg((const uint4*)ha);
                rA1 = __ldcg((const uint4*)(ha + 16));
                if (hasB) {
                    const uint32_t* wp = &Wrow[c * 32 + bk * 16];
#pragma unroll
                    for (int q = 0; q < 4; q++)
                        rB[q] = *(const uint4*)(wp + q * 4);
                }
            };
            auto st = [&](int buf) {
                {
                    int mfr = ar >> 4, rr = ar & 15;
                    int kf1 = aoct >> 1, oo = aoct & 1;
                    int reg = oo * 2 + (rr >> 3);
                    int base1 = buf * 2048 + ((kf1 * 4 + mfr) * 32 + (rr & 7) * 4) * 4 + reg;
                    int base2 = buf * 2048 + (((kf1 + 2) * 4 + mfr) * 32 + (rr & 7) * 4) * 4 + reg;
                    const uint32_t* p0 = (const uint32_t*)&rA0;
                    const uint32_t* p1 = (const uint32_t*)&rA1;
#pragma unroll
                    for (int e = 0; e < 4; e++) {
                        sA[base1 + e * 4] = p0[e];
                        sA[base2 + e * 4] = p1[e];
                    }
                }
                if (hasB) {
                    int nfr = br >> 3, nl = br & 7;
#pragma unroll
                    for (int q = 0; q < 4; q++) {
                        int o = bk * 4 + q;
                        int kf = o >> 1, oo = o & 1;
                        int base = buf * 3072 + ((kf * 12 + nfr) * 32 + nl * 4) * 2 + oo;
                        const uint32_t* p = (const uint32_t*)&rB[q];
#pragma unroll
                        for (int e = 0; e < 4; e++)
                            sB[base + e * 2] = p[e];
                    }
                }
            };
            auto comp = [&](int buf) {
#pragma unroll
                for (int kf = 0; kf < 4; kf++) {
                    uint4 a[2]; uint2 b[3];
#pragma unroll
                    for (int m = 0; m < 2; m++)
                        a[m] = *(const uint4*)&sA[buf * 2048 + ((kf * 4 + wm * 2 + m) * 32 + lane) * 4];
#pragma unroll
                    for (int gt = 0; gt < 3; gt++)
                        b[gt] = *(const uint2*)&sB[buf * 3072 + ((kf * 12 + gt * 4 + wn) * 32 + lane) * 2];
#pragma unroll
                    for (int m = 0; m < 2; m++)
#pragma unroll
                        for (int gt = 0; gt < 3; gt++)
                            mma16f(acc[m][gt], (const uint32_t*)&a[m], (const uint32_t*)&b[gt]);
                }
            };

            ld(0); st(0);
            __syncthreads();
            for (int c = 0; c < NCH; c++) {
                int buf = c & 1;
                if (c + 1 < NCH) ld(c + 1);
                comp(buf);
                if (c + 1 < NCH) {
                    st(buf ^ 1);
                    __syncthreads();
                }
            }

            // ---- fused gate epilogue + fp16 round + scatter ----
#pragma unroll
            for (int m = 0; m < 2; m++) {
#pragma unroll
                for (int half = 0; half < 2; half++) {
                    int idx = m * 2 + half;
                    int g = gE[idx];
                    bool valid = (tstep < cntE[idx]);
                    size_t abase = (size_t)(stE[idx] + tstep) * H3;
                    float hv[2];
#pragma unroll
                    for (int cp = 0; cp < 2; cp++) {
                        int jj = jj0 + cp;
                        float xr, xz, xn;
                        if (valid) {
                            xr = xg[abase + jj];
                            xz = xg[abase + Hdim + jj];
                            xn = xg[abase + 2 * Hdim + jj];
                        } else {
                            xr = biv[cp]; xz = biv[2 + cp]; xn = biv[4 + cp];
                        }
                        int e = half * 2 + cp;
                        float r  = 1.f / (1.f + expf(-(xr + acc[m][0][e] + bhv[cp])));
                        float z  = 1.f / (1.f + expf(-(xz + acc[m][1][e] + bhv[2 + cp])));
                        float nn = tanhf(xn + r * (acc[m][2][e] + bhv[4 + cp]));
                        float hp = __ldcg(&hin[g * Hdim + jj]);
                        hv[cp] = (1.f - z) * nn + z * hp;
                        hout[g * Hdim + jj] = hv[cp];
                        if (valid)
                            out[(size_t)(stE[idx] + tstep) * (2 * Hdim) + (size_t)dir * Hdim + jj] = hv[cp];
                    }
                    ho16[(g * Hdim + jj0) / 2] = pack2h(hv[0], hv[1]);
                }
            }
        }

        // ---- grid barrier between steps (all CTAs arrive) ----
        if (s + 1 < Ldim) {
            __threadfence();
            __syncthreads();
            if (tid == 0) {
                unsigned tgt = (unsigned)(s + 1) * STEP_CTAS;
                atomicAdd(&g_barcnt, 1u);
                while (*(volatile unsigned*)&g_barcnt < tgt) { }
            }
            __syncthreads();
        }
    }
}

// ---------------- host launcher ----------------
extern "C" void kernel_launch(void* const* d_in, const int* in_sizes, int n_in,
                              void* d_out, int out_size)
{
    int nAtoms = in_sizes[0] / Hdim;

    const float* h_atom = (const float*)d_in[0];
    int iBatch, iBias, iWihF, iWhhF, iBihF, iBhhF, iWihB, iWhhB, iBihB, iBhhB;
    if (in_sizes[1] == nAtoms) {
        iBatch = 1; iBias = 2; iWihF = 3; iWhhF = 4; iBihF = 5; iBhhF = 6;
        iWihB = 7; iWhhB = 8; iBihB = 9; iBhhB = 10;
    } else {
        iBias = 1; iWihF = 2; iWhhF = 3; iBihF = 4; iBhhF = 5;
        iWihB = 6; iWhhB = 7; iBihB = 8; iBhhB = 9; iBatch = 10;
    }

    const int*   batch = (const int*)d_in[iBatch];
    const float* bias  = (const float*)d_in[iBias];
    const float* wihf  = (const float*)d_in[iWihF];
    const float* whhf  = (const float*)d_in[iWhhF];
    const float* bihf  = (const float*)d_in[iBihF];
    const float* bhhf  = (const float*)d_in[iBhhF];
    const float* wihb  = (const float*)d_in[iWihB];
    const float* whhb  = (const float*)d_in[iWhhB];
    const float* bihb  = (const float*)d_in[iBihB];
    const float* bhhb  = (const float*)d_in[iBhhB];
    float* out = (float*)d_out;

    k_meta<<<1, 512>>>(batch, nAtoms);

    dim3 gw(WELEM / 4 / 256, 4);
    k_round_w<<<gw, 256>>>(wihf, whhf, wihb, whhb);

    int n4 = nAtoms * Hdim / 4;
    k_message<<<(n4 + 255) / 256, 256>>>(h_atom, bias, n4);

    k_h0<<<Gdim, 256>>>(h_atom);

    dim3 gg(H3 / 128, (nAtoms + 127) / 128, 2);
    k_gemm_f16<<<gg, 256>>>(bihf, bihb, nAtoms);

    // persistent recurrence: one launch, 256 CTAs, internal grid barrier
    dim3 gs(Hdim / 32, Gdim / 64, 2);
    k_step_persist<<<gs, 256>>>(bhhf, bihf, bhhb, bihb, out);
}

// round 16
// speedup vs baseline: 1.5266x; 1.2986x over previous
#include <cuda_runtime.h>
#include <cuda_fp16.h>
#include <math.h>
#include <stdint.h>

#define Hdim 1024
#define H3   3072
#define Gdim 256
#define Ldim 128
#define NMAX 16384
#define WELEM (H3 * Hdim)

// ---------------- scratch (device globals; no allocations) ----------------
__device__ uint32_t g_msg16[NMAX * Hdim / 2];        // fp16x2 rounded message
__device__ uint32_t g_w16[4][WELEM / 2];             // fp16x2 weights: 0=ih_f 1=hh_f 2=ih_b 3=hh_b
__device__ float    g_xg[2][(size_t)NMAX * H3];
__device__ float    g_h[2][2][Gdim * Hdim];          // fp32 hidden (exact carry)
__device__ uint32_t g_h16[2][2][Gdim * Hdim / 2];    // fp16x2 rounded hidden (mma operand)
__device__ int      g_start[Gdim + 1];
__device__ int      g_tilemax[Gdim / 64];            // per-64-graph-tile max count
__device__ unsigned g_bar8[2][4];                    // per-(dir, gtile) barrier (32 CTAs each)

// ---------------- helpers ----------------
__device__ __forceinline__ uint32_t pack2h(float x, float y) {
    __half2 h = __halves2half2(__float2half_rn(x), __float2half_rn(y));
    return *reinterpret_cast<uint32_t*>(&h);
}
__device__ __forceinline__ void mma16f(float* d, const uint32_t* a, const uint32_t* b) {
    asm volatile(
        "mma.sync.aligned.m16n8k16.row.col.f32.f16.f16.f32 "
        "{%0,%1,%2,%3}, {%4,%5,%6,%7}, {%8,%9}, {%0,%1,%2,%3};\n"
        : "+f"(d[0]), "+f"(d[1]), "+f"(d[2]), "+f"(d[3])
        : "r"(a[0]), "r"(a[1]), "r"(a[2]), "r"(a[3]), "r"(b[0]), "r"(b[1]));
}

// ---------------- meta: segment starts + per-tile max + barrier reset ----------------
__global__ void k_meta(const int* __restrict__ batch, int n) {
    __shared__ int smax[Gdim / 64];
    int g = threadIdx.x;
    if (g < 8) ((unsigned*)g_bar8)[g] = 0;
    if (g < Gdim / 64) smax[g] = 0;
    __syncthreads();
    if (g <= Gdim) {
        int lo = 0, hi = n;
        while (lo < hi) {
            int mid = (lo + hi) >> 1;
            if (batch[mid] < g) lo = mid + 1; else hi = mid;
        }
        g_start[g] = lo;
    }
    __syncthreads();
    if (g < Gdim) {
        int gg = g + 1;
        int lo = 0, hi = n;
        while (lo < hi) {
            int mid = (lo + hi) >> 1;
            if (batch[mid] < gg) lo = mid + 1; else hi = mid;
        }
        int cnt = lo - g_start[g];
        atomicMax(&smax[g >> 6], cnt);
    }
    __syncthreads();
    if (g < Gdim / 64) g_tilemax[g] = smax[g];
}

// ---------------- weight round (fp32 -> fp16) ----------------
__global__ void k_round_w(const float* __restrict__ w0, const float* __restrict__ w1,
                          const float* __restrict__ w2, const float* __restrict__ w3) {
    int which = blockIdx.y;
    const float* src = which == 0 ? w0 : which == 1 ? w1 : which == 2 ? w2 : w3;
    int i = blockIdx.x * blockDim.x + threadIdx.x;
    if (i >= WELEM / 4) return;
    float4 v = ((const float4*)src)[i];
    ((uint2*)g_w16[which])[i] = make_uint2(pack2h(v.x, v.y), pack2h(v.z, v.w));
}

// ---------------- message = relu(h_atom + bias) -> fp16 ----------------
__global__ void k_message(const float* __restrict__ h_atom,
                          const float* __restrict__ bias, int n4) {
    int i = blockIdx.x * blockDim.x + threadIdx.x;
    if (i >= n4) return;
    float4 v = ((const float4*)h_atom)[i];
    float4 b = ((const float4*)bias)[i & (Hdim / 4 - 1)];
    v.x = fmaxf(v.x + b.x, 0.f);
    v.y = fmaxf(v.y + b.y, 0.f);
    v.z = fmaxf(v.z + b.z, 0.f);
    v.w = fmaxf(v.w + b.w, 0.f);
    ((uint2*)g_msg16)[i] = make_uint2(pack2h(v.x, v.y), pack2h(v.z, v.w));
}

// ---------------- h0 = segment max (4-row MLP); fp32 + fp16, both dirs ----------------
__global__ void k_h0(const float* __restrict__ h_atom) {
    int g = blockIdx.x;
    int c = threadIdx.x * 4;
    int s0 = g_start[g], s1 = g_start[g + 1];
    float4 m0 = make_float4(-3.4e38f, -3.4e38f, -3.4e38f, -3.4e38f);
    float4 m1 = m0, m2 = m0, m3 = m0;
    int r = s0;
    for (; r + 4 <= s1; r += 4) {
        float4 v0 = *(const float4*)&h_atom[(size_t)(r + 0) * Hdim + c];
        float4 v1 = *(const float4*)&h_atom[(size_t)(r + 1) * Hdim + c];
        float4 v2 = *(const float4*)&h_atom[(size_t)(r + 2) * Hdim + c];
        float4 v3 = *(const float4*)&h_atom[(size_t)(r + 3) * Hdim + c];
        m0.x = fmaxf(m0.x, v0.x); m0.y = fmaxf(m0.y, v0.y); m0.z = fmaxf(m0.z, v0.z); m0.w = fmaxf(m0.w, v0.w);
        m1.x = fmaxf(m1.x, v1.x); m1.y = fmaxf(m1.y, v1.y); m1.z = fmaxf(m1.z, v1.z); m1.w = fmaxf(m1.w, v1.w);
        m2.x = fmaxf(m2.x, v2.x); m2.y = fmaxf(m2.y, v2.y); m2.z = fmaxf(m2.z, v2.z); m2.w = fmaxf(m2.w, v2.w);
        m3.x = fmaxf(m3.x, v3.x); m3.y = fmaxf(m3.y, v3.y); m3.z = fmaxf(m3.z, v3.z); m3.w = fmaxf(m3.w, v3.w);
    }
    for (; r < s1; r++) {
        float4 v = *(const float4*)&h_atom[(size_t)r * Hdim + c];
        m0.x = fmaxf(m0.x, v.x); m0.y = fmaxf(m0.y, v.y); m0.z = fmaxf(m0.z, v.z); m0.w = fmaxf(m0.w, v.w);
    }
    float4 m;
    m.x = fmaxf(fmaxf(m0.x, m1.x), fmaxf(m2.x, m3.x));
    m.y = fmaxf(fmaxf(m0.y, m1.y), fmaxf(m2.y, m3.y));
    m.z = fmaxf(fmaxf(m0.z, m1.z), fmaxf(m2.z, m3.z));
    m.w = fmaxf(fmaxf(m0.w, m1.w), fmaxf(m2.w, m3.w));
    if (s1 == s0) m = make_float4(0.f, 0.f, 0.f, 0.f);
    int fi = g * Hdim + c;
    uint2 p = make_uint2(pack2h(m.x, m.y), pack2h(m.z, m.w));
#pragma unroll
    for (int d = 0; d < 2; d++) {
        *(float4*)&g_h[d][0][fi] = m;
        ((uint2*)g_h16[d][0])[fi / 4] = p;
    }
}

// =====================================================================
// Input GEMM (fp16): XG[n x 3072] = msg @ W_ih^T + b_ih
// Block 128m x 128n, K-chunk 16, 8 warps (2m x 4n), warp 64x32.
// =====================================================================
__global__ void __launch_bounds__(256) k_gemm_f16(
    const float* __restrict__ bi_f, const float* __restrict__ bi_b, int n)
{
    __shared__ uint32_t sA[2048], sB[2048];
    int dir = blockIdx.z;
    const uint32_t* W = g_w16[dir * 2];
    const float* Bv = dir ? bi_b : bi_f;
    float* XG = g_xg[dir];
    int n0 = blockIdx.x * 128;
    int m0 = blockIdx.y * 128;
    int tid = threadIdx.x, lane = tid & 31, wid = tid >> 5;
    int wm = wid >> 2, wn = wid & 3;

    int ar = tid >> 1, ao = tid & 1;
    int br = tid >> 1, bo = tid & 1;

    float acc[4][4][4];
#pragma unroll
    for (int m = 0; m < 4; m++)
#pragma unroll
        for (int q = 0; q < 4; q++)
#pragma unroll
            for (int e = 0; e < 4; e++) acc[m][q][e] = 0.f;

    uint4 pA, pB;

    auto ld = [&](int k0) {
        int rg = m0 + ar;
        if (rg < n) pA = *(const uint4*)&g_msg16[rg * (Hdim / 2) + (k0 + ao * 8) / 2];
        else        pA = make_uint4(0, 0, 0, 0);
        pB = *(const uint4*)&W[(size_t)(n0 + br) * (Hdim / 2) + (k0 + bo * 8) / 2];
    };
    auto st = [&](int buf) {
        int mfr = ar >> 4, rh = (ar >> 3) & 1, reg = ao * 2 + rh;
        int base = buf * 1024 + (mfr * 32 + (ar & 7) * 4) * 4 + reg;
        const uint32_t* p = (const uint32_t*)&pA;
#pragma unroll
        for (int i = 0; i < 4; i++) sA[base + i * 4] = p[i];
        int nfr = br >> 3, nl = br & 7;
        int base2 = buf * 1024 + (nfr * 32 + nl * 4) * 2 + bo;
        const uint32_t* q = (const uint32_t*)&pB;
#pragma unroll
        for (int i = 0; i < 4; i++) sB[base2 + i * 2] = q[i];
    };
    auto comp = [&](int buf) {
        uint4 a[4]; uint2 b[4];
#pragma unroll
        for (int m = 0; m < 4; m++)
            a[m] = *(const uint4*)&sA[buf * 1024 + ((wm * 4 + m) * 32 + lane) * 4];
#pragma unroll
        for (int q = 0; q < 4; q++)
            b[q] = *(const uint2*)&sB[buf * 1024 + ((wn * 4 + q) * 32 + lane) * 2];
#pragma unroll
        for (int m = 0; m < 4; m++)
#pragma unroll
            for (int q = 0; q < 4; q++)
                mma16f(acc[m][q], (const uint32_t*)&a[m], (const uint32_t*)&b[q]);
    };

    ld(0); st(0); __syncthreads();
    for (int c = 0; c < Hdim / 16; c++) {
        int buf = c & 1;
        if (c + 1 < Hdim / 16) ld((c + 1) * 16);
        comp(buf);
        if (c + 1 < Hdim / 16) { st(buf ^ 1); __syncthreads(); }
    }

#pragma unroll
    for (int m = 0; m < 4; m++)
#pragma unroll
        for (int half = 0; half < 2; half++) {
            int row = m0 + wm * 64 + m * 16 + (lane >> 2) + half * 8;
            if (row < n) {
#pragma unroll
                for (int q = 0; q < 4; q++) {
                    int col = n0 + wn * 32 + q * 8 + (lane & 3) * 2;
                    float2 o;
                    o.x = acc[m][q][half * 2 + 0] + Bv[col];
                    o.y = acc[m][q][half * 2 + 1] + Bv[col + 1];
                    *(float2*)&XG[(size_t)row * H3 + col] = o;
                }
            }
        }
}

// =====================================================================
// PERSISTENT GRU step kernel (R12 structure: K-chunk 32, 3 smem buffers,
// 2-deep register prefetch, CTA 64g x 96n, grid 256, 2/SM).
// NEW: per-(dir, gtile) barriers (32 CTAs each) decouple the 8 chains;
// fwd groups retire wholesale; next-step xg rows L2-prefetched.
// =====================================================================
#define NCH 32   // 1024 / 32

__global__ void __launch_bounds__(256, 2) k_step_persist(
    const float* __restrict__ bhh_f, const float* __restrict__ bih_f,
    const float* __restrict__ bhh_b, const float* __restrict__ bih_b,
    float* __restrict__ out)
{
    __shared__ uint32_t sA[3 * 1024], sB[3 * 1536];
    int dir = blockIdx.z;
    int gy = blockIdx.y;
    const uint32_t* W = g_w16[dir * 2 + 1];
    const float* Bh = dir ? bhh_b : bhh_f;
    const float* Bi = dir ? bih_b : bih_f;
    const float* xg = g_xg[dir];
    int j0 = blockIdx.x * 32;
    int g0 = gy * 64;
    int tid = threadIdx.x, lane = tid & 31, wid = tid >> 5;
    int wm = wid >> 2, wn = wid & 3;
    int tmax = g_tilemax[gy];

    // loader indices (invariant)
    int ar = tid >> 2, aoct = tid & 3;
    bool hasB = tid < 192;
    int br = tid >> 1, bk = tid & 1;
    const uint32_t* Wrow = &W[(size_t)((br >> 5) * Hdim + j0 + (br & 31)) * (Hdim / 2)];

    // epilogue invariants
    int jj0 = j0 + wn * 8 + (lane & 3) * 2;
    float bhv[6], biv[6];
#pragma unroll
    for (int t3 = 0; t3 < 3; t3++) {
        bhv[t3 * 2 + 0] = Bh[t3 * Hdim + jj0];
        bhv[t3 * 2 + 1] = Bh[t3 * Hdim + jj0 + 1];
        biv[t3 * 2 + 0] = Bi[t3 * Hdim + jj0];
        biv[t3 * 2 + 1] = Bi[t3 * Hdim + jj0 + 1];
    }
    int gE[4], stE[4], cntE[4];
#pragma unroll
    for (int m = 0; m < 2; m++)
#pragma unroll
        for (int half = 0; half < 2; half++) {
            int idx = m * 2 + half;
            int g = g0 + (wm * 2 + m) * 16 + (lane >> 2) + half * 8;
            gE[idx] = g;
            stE[idx] = g_start[g];
            cntE[idx] = g_start[g + 1] - stE[idx];
        }

    uint4 rA[2], rB0[2], rB1[2];

    for (int s = 0; s < Ldim; s++) {
        int tstep = dir ? (Ldim - 1 - s) : s;

        // forward group retires wholesale (all 32 CTAs share tmax; their
        // barrier is never used afterward -> safe).
        if (dir == 0 && tstep >= tmax) return;

        int par = s & 1;
        const float*    hin  = g_h[dir][par];
        float*          hout = g_h[dir][par ^ 1];
        const uint32_t* h16  = g_h16[dir][par];
        uint32_t*       ho16 = g_h16[dir][par ^ 1];

        float acc[2][3][4];
#pragma unroll
        for (int m = 0; m < 2; m++)
#pragma unroll
            for (int gt = 0; gt < 3; gt++)
#pragma unroll
                for (int e = 0; e < 4; e++) acc[m][gt][e] = 0.f;

        auto ld = [&](int c, int rs) {
            rA[rs] = __ldcg((const uint4*)&h16[(g0 + ar) * (Hdim / 2) + c * 16 + aoct * 4]);
            if (hasB) {
                const uint32_t* wp = &Wrow[c * 16 + bk * 8];
                rB0[rs] = *(const uint4*)wp;
                rB1[rs] = *(const uint4*)(wp + 4);
            }
        };
        auto st = [&](int buf, int rs) {
            {
                int kf = aoct >> 1, oo = aoct & 1;
                int mfr = ar >> 4, rr = ar & 15;
                int reg = oo * 2 + (rr >> 3);
                int base = buf * 1024 + ((kf * 4 + mfr) * 32 + (rr & 7) * 4) * 4 + reg;
                const uint32_t* p = (const uint32_t*)&rA[rs];
#pragma unroll
                for (int e = 0; e < 4; e++) sA[base + e * 4] = p[e];
            }
            if (hasB) {
                int nfr = br >> 3, nl = br & 7;
                int base = buf * 1536 + ((bk * 12 + nfr) * 32 + nl * 4) * 2;
                const uint32_t* p0 = (const uint32_t*)&rB0[rs];
                const uint32_t* p1 = (const uint32_t*)&rB1[rs];
#pragma unroll
                for (int e = 0; e < 4; e++) {
                    sB[base + e * 2 + 0] = p0[e];
                    sB[base + e * 2 + 1] = p1[e];
                }
            }
        };
        auto comp = [&](int buf) {
#pragma unroll
            for (int kf = 0; kf < 2; kf++) {
                uint4 a[2]; uint2 b[3];
#pragma unroll
                for (int m = 0; m < 2; m++)
                    a[m] = *(const uint4*)&sA[buf * 1024 + ((kf * 4 + wm * 2 + m) * 32 + lane) * 4];
#pragma unroll
                for (int gt = 0; gt < 3; gt++)
                    b[gt] = *(const uint2*)&sB[buf * 1536 + ((kf * 12 + gt * 4 + wn) * 32 + lane) * 2];
#pragma unroll
                for (int m = 0; m < 2; m++)
#pragma unroll
                    for (int gt = 0; gt < 3; gt++)
                        mma16f(acc[m][gt], (const uint32_t*)&a[m], (const uint32_t*)&b[gt]);
            }
        };

        ld(0, 0); st(0, 0); ld(1, 1);
        __syncthreads();
#pragma unroll 4
        for (int c = 0; c < NCH; c++) {
            int buf = c % 3;
            if (c + 2 < NCH) ld(c + 2, c & 1);
            comp(buf);
            if (c + 1 < NCH) {
                st((c + 1) % 3, (c + 1) & 1);
                __syncthreads();
            }
        }

        // ---- fused gate epilogue + fp16 round + scatter ----
#pragma unroll
        for (int m = 0; m < 2; m++) {
#pragma unroll
            for (int half = 0; half < 2; half++) {
                int idx = m * 2 + half;
                int g = gE[idx];
                bool valid = (tstep < cntE[idx]);
                size_t abase = (size_t)(stE[idx] + tstep) * H3;
                float hv[2];
#pragma unroll
                for (int cp = 0; cp < 2; cp++) {
                    int jj = jj0 + cp;
                    float xr, xz, xn;
                    if (valid) {
                        xr = xg[abase + jj];
                        xz = xg[abase + Hdim + jj];
                        xn = xg[abase + 2 * Hdim + jj];
                    } else {
                        xr = biv[cp]; xz = biv[2 + cp]; xn = biv[4 + cp];
                    }
                    int e = half * 2 + cp;
                    float r  = 1.f / (1.f + expf(-(xr + acc[m][0][e] + bhv[cp])));
                    float z  = 1.f / (1.f + expf(-(xz + acc[m][1][e] + bhv[2 + cp])));
                    float nn = tanhf(xn + r * (acc[m][2][e] + bhv[4 + cp]));
                    float hp = __ldcg(&hin[g * Hdim + jj]);
                    hv[cp] = (1.f - z) * nn + z * hp;
                    hout[g * Hdim + jj] = hv[cp];
                    if (valid)
                        out[(size_t)(stE[idx] + tstep) * (2 * Hdim) + (size_t)dir * Hdim + jj] = hv[cp];
                }
                ho16[(g * Hdim + jj0) / 2] = pack2h(hv[0], hv[1]);
            }
        }

        // ---- L2 prefetch of next step's xg rows (register-free) ----
        if (s + 1 < Ldim) {
            int tnext = dir ? (tstep - 1) : (tstep + 1);
            if ((lane & 3) == 0 && tnext >= 0) {
#pragma unroll
                for (int idx = 0; idx < 4; idx++) {
                    if (tnext < cntE[idx]) {
                        const float* p = &xg[(size_t)(stE[idx] + tnext) * H3 + jj0];
                        asm volatile("prefetch.global.L2 [%0];" :: "l"(p));
                        asm volatile("prefetch.global.L2 [%0];" :: "l"(p + Hdim));
                        asm volatile("prefetch.global.L2 [%0];" :: "l"(p + 2 * Hdim));
                    }
                }
            }

            // ---- per-(dir, gtile) barrier: 32 CTAs ----
            __threadfence();
            __syncthreads();
            if (tid == 0) {
                unsigned tgt = (unsigned)(s + 1) * 32u;
                atomicAdd(&g_bar8[dir][gy], 1u);
                while (*(volatile unsigned*)&g_bar8[dir][gy] < tgt) { }
            }
            __syncthreads();
        }
    }
}

// ---------------- host launcher ----------------
extern "C" void kernel_launch(void* const* d_in, const int* in_sizes, int n_in,
                              void* d_out, int out_size)
{
    int nAtoms = in_sizes[0] / Hdim;

    const float* h_atom = (const float*)d_in[0];
    int iBatch, iBias, iWihF, iWhhF, iBihF, iBhhF, iWihB, iWhhB, iBihB, iBhhB;
    if (in_sizes[1] == nAtoms) {
        iBatch = 1; iBias = 2; iWihF = 3; iWhhF = 4; iBihF = 5; iBhhF = 6;
        iWihB = 7; iWhhB = 8; iBihB = 9; iBhhB = 10;
    } else {
        iBias = 1; iWihF = 2; iWhhF = 3; iBihF = 4; iBhhF = 5;
        iWihB = 6; iWhhB = 7; iBihB = 8; iBhhB = 9; iBatch = 10;
    }

    const int*   batch = (const int*)d_in[iBatch];
    const float* bias  = (const float*)d_in[iBias];
    const float* wihf  = (const float*)d_in[iWihF];
    const float* whhf  = (const float*)d_in[iWhhF];
    const float* bihf  = (const float*)d_in[iBihF];
    const float* bhhf  = (const float*)d_in[iBhhF];
    const float* wihb  = (const float*)d_in[iWihB];
    const float* whhb  = (const float*)d_in[iWhhB];
    const float* bihb  = (const float*)d_in[iBihB];
    const float* bhhb  = (const float*)d_in[iBhhB];
    float* out = (float*)d_out;

    k_meta<<<1, 512>>>(batch, nAtoms);

    dim3 gw(WELEM / 4 / 256, 4);
    k_round_w<<<gw, 256>>>(wihf, whhf, wihb, whhb);

    int n4 = nAtoms * Hdim / 4;
    k_message<<<(n4 + 255) / 256, 256>>>(h_atom, bias, n4);

    k_h0<<<Gdim, 256>>>(h_atom);

    dim3 gg(H3 / 128, (nAtoms + 127) / 128, 2);
    k_gemm_f16<<<gg, 256>>>(bihf, bihb, nAtoms);

    // persistent recurrence: one launch, 256 CTAs, per-(dir,gtile) barriers
    dim3 gs(Hdim / 32, Gdim / 64, 2);
    k_step_persist<<<gs, 256>>>(bhhf, bihf, bhhb, bihb, out);
}